// round 6
// baseline (speedup 1.0000x reference)
#include <cuda_runtime.h>
#include <stdint.h>

#define N_POS 8192
#define N_NEG 4000
#define N_TOT (N_POS + N_POS * N_NEG)   // 32,776,192 (divisible by 4)
#define N_VEC (N_TOT / 4)               // 8,194,048

// Scratch (allocation-free rule: __device__ globals)
__device__ float          g_pos[N_POS];
__device__ unsigned short g_rowid[N_TOT];          // 65.55 MB
__device__ unsigned int   g_hist[N_POS / 2];       // packed: two u16 counters per word
__device__ unsigned int   g_done;                  // last-block-done counter

// ---------------------------------------------------------------------------
// Pass 1: scan index once (int32 input). Emit u16 row-id per element
// (0xFFFF = pos element), scatter the 8192 pos values, zero hist + counter.
// ---------------------------------------------------------------------------
__global__ void __launch_bounds__(256) mrr_pass1(
    const float* __restrict__ val, const int* __restrict__ idx)
{
    const unsigned int tid = blockIdx.x * blockDim.x + threadIdx.x;
    if (tid < N_POS / 2) g_hist[tid] = 0u;
    if (tid == 0) g_done = 0u;

    const unsigned int stride = gridDim.x * blockDim.x;
    const int4* __restrict__ idx4 = (const int4*)idx;
    ushort4* __restrict__ rid4 = (ushort4*)g_rowid;

    #pragma unroll 4
    for (unsigned int v = tid; v < N_VEC; v += stride) {
        int4 q = idx4[v];
        unsigned int j0 = (unsigned int)q.x;
        unsigned int j1 = (unsigned int)q.y;
        unsigned int j2 = (unsigned int)q.z;
        unsigned int j3 = (unsigned int)q.w;
        unsigned int base = v * 4u;

        ushort4 r;
        if (j0 < N_POS) { r.x = 0xFFFFu; g_pos[j0] = val[base + 0]; }
        else            { r.x = (unsigned short)((j0 - N_POS) / (unsigned)N_NEG); }
        if (j1 < N_POS) { r.y = 0xFFFFu; g_pos[j1] = val[base + 1]; }
        else            { r.y = (unsigned short)((j1 - N_POS) / (unsigned)N_NEG); }
        if (j2 < N_POS) { r.z = 0xFFFFu; g_pos[j2] = val[base + 2]; }
        else            { r.z = (unsigned short)((j2 - N_POS) / (unsigned)N_NEG); }
        if (j3 < N_POS) { r.w = 0xFFFFu; g_pos[j3] = val[base + 3]; }
        else            { r.w = (unsigned short)((j3 - N_POS) / (unsigned)N_NEG); }

        rid4[v] = r;
    }
}

// ---------------------------------------------------------------------------
// Pass 2: SMEM-privatized histogram with minority-side counting, 2 waves to
// absorb single-wave CTA spread. Last block to finish fuses the finalize
// (ranks -> sample_mrr -> deterministic mean), reusing s_pos as reduction
// scratch so static smem stays at exactly 48KB (4 blocks/SM).
//   p >  0 -> count (v >  p);  p <= 0 -> count (v <= p)
// inc = (v > p) XOR (p <= 0). Per-row global count <= 4000, u16 halves safe.
// ---------------------------------------------------------------------------
#define P2_BLOCKS 1184
#define P2_THREADS 512

__global__ void __launch_bounds__(P2_THREADS) mrr_pass2(
    const float* __restrict__ val, float* __restrict__ out)
{
    __shared__ __align__(16) float s_pos[N_POS];   // 32768 B (reused for reduction)
    __shared__ unsigned int s_hist[N_POS / 2];     // 16384 B
    __shared__ unsigned int s_is_last;

    const int t = threadIdx.x;
    for (int i = t; i < N_POS; i += P2_THREADS)     s_pos[i]  = g_pos[i];
    for (int i = t; i < N_POS / 2; i += P2_THREADS) s_hist[i] = 0u;
    __syncthreads();

    const unsigned int tid = blockIdx.x * P2_THREADS + t;
    const unsigned int stride = gridDim.x * P2_THREADS;
    const float4*  __restrict__ v4 = (const float4*)val;
    const ushort4* __restrict__ r4 = (const ushort4*)g_rowid;

    #pragma unroll 2
    for (unsigned int v = tid; v < N_VEC; v += stride) {
        float4  f = v4[v];
        ushort4 r = r4[v];
        {
            float p = s_pos[r.x & 0x1FFFu];
            if (r.x != 0xFFFFu && ((f.x > p) != (p <= 0.0f)))
                atomicAdd(&s_hist[r.x >> 1], 1u << ((r.x & 1u) << 4));
        }
        {
            float p = s_pos[r.y & 0x1FFFu];
            if (r.y != 0xFFFFu && ((f.y > p) != (p <= 0.0f)))
                atomicAdd(&s_hist[r.y >> 1], 1u << ((r.y & 1u) << 4));
        }
        {
            float p = s_pos[r.z & 0x1FFFu];
            if (r.z != 0xFFFFu && ((f.z > p) != (p <= 0.0f)))
                atomicAdd(&s_hist[r.z >> 1], 1u << ((r.z & 1u) << 4));
        }
        {
            float p = s_pos[r.w & 0x1FFFu];
            if (r.w != 0xFFFFu && ((f.w > p) != (p <= 0.0f)))
                atomicAdd(&s_hist[r.w >> 1], 1u << ((r.w & 1u) << 4));
        }
    }
    __syncthreads();

    // Flush packed words: whole-word add is safe (global per-row total <= 4000).
    for (int i = t; i < N_POS / 2; i += P2_THREADS) {
        unsigned int h = s_hist[i];
        if (h) atomicAdd(&g_hist[i], h);
    }

    // Last-block-done election
    __threadfence();
    __syncthreads();
    if (t == 0) s_is_last = (atomicAdd(&g_done, 1u) == (unsigned)gridDim.x - 1u);
    __syncthreads();
    if (!s_is_last) return;

    // ---- Finalize (this block only) ----
    __threadfence();  // acquire all blocks' g_hist flushes
    double local = 0.0;
    float  samp[N_POS / P2_THREADS];  // 16 rows per thread
    #pragma unroll
    for (int k = 0; k < N_POS / P2_THREADS; k++) {
        int r = t + k * P2_THREADS;
        unsigned int h = g_hist[r >> 1];
        unsigned int c = (r & 1) ? (h >> 16) : (h & 0xFFFFu);
        float p = s_pos[r];           // still holds pos values
        unsigned int cnt_gt = (p > 0.0f) ? c : ((unsigned)N_NEG - c);
        float s = 1.0f / (float)(1u + cnt_gt);
        samp[k] = s;
        local += (double)s;
    }
    __syncthreads();                  // done reading s_pos; reuse as scratch
    #pragma unroll
    for (int k = 0; k < N_POS / P2_THREADS; k++)
        out[1 + t + k * P2_THREADS] = samp[k];

    double* ssum = (double*)s_pos;    // 512 doubles = 4KB, fits in 32KB
    ssum[t] = local;
    __syncthreads();
    for (int off = P2_THREADS / 2; off > 0; off >>= 1) {
        if (t < off) ssum[t] += ssum[t + off];
        __syncthreads();
    }
    if (t == 0) out[0] = (float)(ssum[0] / (double)N_POS);
}

extern "C" void kernel_launch(void* const* d_in, const int* in_sizes, int n_in,
                              void* d_out, int out_size)
{
    const float* val = (const float*)d_in[0];
    const int*   idx = (const int*)d_in[1];
    float*       out = (float*)d_out;

    mrr_pass1<<<2048, 256>>>(val, idx);
    mrr_pass2<<<P2_BLOCKS, P2_THREADS>>>(val, out);  // 2 waves @ 4 blocks/SM
}

// round 7
// speedup vs baseline: 1.1872x; 1.1872x over previous
#include <cuda_runtime.h>
#include <stdint.h>

#define N_POS 8192
#define N_NEG 4000u
#define N_TOT (N_POS + N_POS * (int)N_NEG)  // 32,776,192 (divisible by 4)
#define N_VEC (N_TOT / 4)                   // 8,194,048

#define HIST_WORDS (N_POS / 2)              // 4096 packed u16x2 words
#define HIST_PAD   32                       // 1 word per 128B line

// Scratch (allocation-free rule: __device__ globals)
__device__ float        g_pos[N_POS];
__device__ unsigned int g_histp[HIST_WORDS * HIST_PAD];  // padded: 512 KB
__device__ unsigned int g_done;

// ---------------------------------------------------------------------------
// Pass 1: pure scan of idx (int32). Scatter the 8192 pos values; zero the
// padded histogram and the done counter. ~131 MB read -> DRAM-bound.
// ---------------------------------------------------------------------------
__global__ void __launch_bounds__(256) mrr_pass1(
    const float* __restrict__ val, const int* __restrict__ idx)
{
    const unsigned int tid = blockIdx.x * blockDim.x + threadIdx.x;
    const unsigned int stride = gridDim.x * blockDim.x;

    for (unsigned int i = tid; i < HIST_WORDS * HIST_PAD; i += stride)
        g_histp[i] = 0u;
    if (tid == 0) g_done = 0u;

    const int4* __restrict__ idx4 = (const int4*)idx;

    #pragma unroll 4
    for (unsigned int v = tid; v < N_VEC; v += stride) {
        int4 q = idx4[v];
        unsigned int base = v * 4u;
        if ((unsigned)q.x < N_POS) g_pos[q.x] = val[base + 0];
        if ((unsigned)q.y < N_POS) g_pos[q.y] = val[base + 1];
        if ((unsigned)q.z < N_POS) g_pos[q.z] = val[base + 2];
        if ((unsigned)q.w < N_POS) g_pos[q.w] = val[base + 3];
    }
}

// ---------------------------------------------------------------------------
// Pass 2: read idx + val together, compute row on the fly, SMEM-privatized
// histogram with minority-side counting:
//   p >  0 -> count (v >  p);  p <= 0 -> count (v <= p)
// inc = (v > p) XOR (p <= 0); fixed up in finalize. Per-row count <= 4000 so
// packed u16 halves never overflow. Flush goes to the PADDED global hist
// (one counter word per 128B line -> no LTS line-queue serialization).
// Last block fuses the finalize. Static smem = exactly 48KB -> 4 blocks/SM.
// ---------------------------------------------------------------------------
#define P2_BLOCKS 592
#define P2_THREADS 512

__global__ void __launch_bounds__(P2_THREADS) mrr_pass2(
    const float* __restrict__ val, const int* __restrict__ idx,
    float* __restrict__ out)
{
    __shared__ __align__(16) float s_pos[N_POS];   // 32768 B (reused in finalize)
    __shared__ unsigned int s_hist[HIST_WORDS];    // 16384 B
    __shared__ unsigned int s_is_last;

    const int t = threadIdx.x;
    for (int i = t; i < N_POS; i += P2_THREADS)      s_pos[i]  = g_pos[i];
    for (int i = t; i < HIST_WORDS; i += P2_THREADS) s_hist[i] = 0u;
    __syncthreads();

    const unsigned int tid = blockIdx.x * P2_THREADS + t;
    const unsigned int stride = gridDim.x * P2_THREADS;
    const float4* __restrict__ v4 = (const float4*)val;
    const int4*   __restrict__ i4 = (const int4*)idx;

    #pragma unroll 2
    for (unsigned int v = tid; v < N_VEC; v += stride) {
        int4   q = i4[v];
        float4 f = v4[v];
        {
            unsigned int j = (unsigned)q.x;
            if (j >= N_POS) {
                unsigned int row = (j - N_POS) / N_NEG;
                float p = s_pos[row];
                if ((f.x > p) != (p <= 0.0f))
                    atomicAdd(&s_hist[row >> 1], 1u << ((row & 1u) << 4));
            }
        }
        {
            unsigned int j = (unsigned)q.y;
            if (j >= N_POS) {
                unsigned int row = (j - N_POS) / N_NEG;
                float p = s_pos[row];
                if ((f.y > p) != (p <= 0.0f))
                    atomicAdd(&s_hist[row >> 1], 1u << ((row & 1u) << 4));
            }
        }
        {
            unsigned int j = (unsigned)q.z;
            if (j >= N_POS) {
                unsigned int row = (j - N_POS) / N_NEG;
                float p = s_pos[row];
                if ((f.z > p) != (p <= 0.0f))
                    atomicAdd(&s_hist[row >> 1], 1u << ((row & 1u) << 4));
            }
        }
        {
            unsigned int j = (unsigned)q.w;
            if (j >= N_POS) {
                unsigned int row = (j - N_POS) / N_NEG;
                float p = s_pos[row];
                if ((f.w > p) != (p <= 0.0f))
                    atomicAdd(&s_hist[row >> 1], 1u << ((row & 1u) << 4));
            }
        }
    }
    __syncthreads();

    // Flush packed words to PADDED global hist (whole-word add is safe:
    // global per-row total <= 4000 so halves can't carry).
    for (int i = t; i < HIST_WORDS; i += P2_THREADS) {
        unsigned int h = s_hist[i];
        if (h) atomicAdd(&g_histp[i * HIST_PAD], h);
    }

    // Last-block-done election
    __threadfence();
    __syncthreads();
    if (t == 0) s_is_last = (atomicAdd(&g_done, 1u) == (unsigned)gridDim.x - 1u);
    __syncthreads();
    if (!s_is_last) return;

    // ---- Finalize (this block only) ----
    __threadfence();  // acquire all blocks' flushes
    double local = 0.0;
    float  samp[N_POS / P2_THREADS];  // 16 rows per thread
    #pragma unroll
    for (int k = 0; k < N_POS / P2_THREADS; k++) {
        int r = t + k * P2_THREADS;
        unsigned int h = g_histp[(r >> 1) * HIST_PAD];
        unsigned int c = (r & 1) ? (h >> 16) : (h & 0xFFFFu);
        float p = s_pos[r];           // still holds pos values
        unsigned int cnt_gt = (p > 0.0f) ? c : (N_NEG - c);
        float s = 1.0f / (float)(1u + cnt_gt);
        samp[k] = s;
        local += (double)s;
    }
    __syncthreads();                  // done reading s_pos; reuse as scratch
    #pragma unroll
    for (int k = 0; k < N_POS / P2_THREADS; k++)
        out[1 + t + k * P2_THREADS] = samp[k];

    double* ssum = (double*)s_pos;    // 512 doubles = 4KB
    ssum[t] = local;
    __syncthreads();
    for (int off = P2_THREADS / 2; off > 0; off >>= 1) {
        if (t < off) ssum[t] += ssum[t + off];
        __syncthreads();
    }
    if (t == 0) out[0] = (float)(ssum[0] / (double)N_POS);
}

extern "C" void kernel_launch(void* const* d_in, const int* in_sizes, int n_in,
                              void* d_out, int out_size)
{
    const float* val = (const float*)d_in[0];
    const int*   idx = (const int*)d_in[1];
    float*       out = (float*)d_out;

    mrr_pass1<<<2048, 256>>>(val, idx);
    mrr_pass2<<<P2_BLOCKS, P2_THREADS>>>(val, idx, out);
}